// round 12
// baseline (speedup 1.0000x reference)
#include <cuda_runtime.h>
#include <cuda_fp16.h>
#include <math.h>
#include <stdint.h>

#define MM   16384
#define Cc   1024
#define Tt   2048
#define EPSV 1e-6f

// ---------------------------------------------------------------------------
// Scratch (__device__ globals; no allocation allowed)
// ---------------------------------------------------------------------------
__device__ __half g_xh[MM * Cc];                  // x fp16; reused for q*v
__device__ __half g_zh[MM * Cc];                  // scan state (unnormalized z)
__device__ float  g_v [MM * Cc];
__device__ float  g_u [2 * MM * 128];             // split-K partial U buffers
__device__ __half g_sch[MM * 128];
__device__ float  g_pmax[8 * MM];
__device__ float  g_rinv[MM];
__device__ float  g_c1[64];
__device__ float  g_zero[2048];                   // zero bias (static init 0)
__device__ __half g_aW[2048 * 1024];              // attn_W^T  [N][K]
__device__ __half g_fW[128 * 1024];               // [W1|W2]^T [N][K]
__device__ __half g_oW[1024 * 128];               // out_W^T   [N][K]
__device__ __half g_pW[1024 * 1024];              // proj_W^T  [N][K]
__device__ unsigned g_cnt = 0, g_gen = 0;         // grid barrier state

// ---------------------------------------------------------------------------
__device__ __forceinline__ uint32_t smem_u32(const void* p) {
    uint32_t a;
    asm("{ .reg .u64 t; cvta.to.shared.u64 t, %1; cvt.u32.u64 %0, t; }"
        : "=r"(a) : "l"(p));
    return a;
}
__device__ __forceinline__ void cp16(uint32_t dst, const void* src) {
    asm volatile("cp.async.cg.shared.global [%0], [%1], 16;"
                 :: "r"(dst), "l"(src));
}
#define CP_COMMIT() asm volatile("cp.async.commit_group;")
#define CP_WAIT1()  asm volatile("cp.async.wait_group 1;")
#define CP_WAIT0()  asm volatile("cp.async.wait_group 0;")

__device__ __forceinline__ void ldmA(uint32_t* a, uint32_t addr) {
    asm volatile("ldmatrix.sync.aligned.m8n8.x4.shared.b16 {%0,%1,%2,%3}, [%4];"
                 : "=r"(a[0]), "=r"(a[1]), "=r"(a[2]), "=r"(a[3]) : "r"(addr));
}
__device__ __forceinline__ void ldmB(uint32_t* b, uint32_t addr) {
    asm volatile("ldmatrix.sync.aligned.m8n8.x2.shared.b16 {%0,%1}, [%2];"
                 : "=r"(b[0]), "=r"(b[1]) : "r"(addr));
}
__device__ __forceinline__ void mma16816(float* c, const uint32_t* a,
                                         const uint32_t* b) {
    asm volatile("mma.sync.aligned.m16n8k16.row.col.f32.f16.f16.f32 "
                 "{%0,%1,%2,%3}, {%4,%5,%6,%7}, {%8,%9}, {%0,%1,%2,%3};"
                 : "+f"(c[0]), "+f"(c[1]), "+f"(c[2]), "+f"(c[3])
                 : "r"(a[0]), "r"(a[1]), "r"(a[2]), "r"(a[3]),
                   "r"(b[0]), "r"(b[1]));
}
__device__ __forceinline__ uint32_t roundH2(float a, float b) {
    __half2 hp = __halves2half2(__float2half_rn(a), __float2half_rn(b));
    return *(uint32_t*)&hp;
}
__device__ __forceinline__ float get_rinv(const float* pmax, int r) {
    float m = 0.0f;
    #pragma unroll
    for (int j = 0; j < 8; j++) m = fmaxf(m, pmax[j * MM + r]);
    return 1.0f / (m + EPSV);
}

// ---------------------------------------------------------------------------
// Grid-wide barrier among co-resident CTAs (generation counting; replay-safe:
// counter self-resets every use, generation only grows).
// ---------------------------------------------------------------------------
__device__ __forceinline__ void grid_sync(unsigned nCta) {
    __syncthreads();
    if (threadIdx.x == 0) {
        __threadfence();
        unsigned gen = atomicAdd(&g_gen, 0u);
        if (atomicAdd(&g_cnt, 1u) == nCta - 1u) {
            atomicExch(&g_cnt, 0u);
            __threadfence();
            atomicAdd(&g_gen, 1u);
        } else {
            while (atomicAdd(&g_gen, 0u) == gen) { __nanosleep(64); }
        }
        __threadfence();
    }
    __syncthreads();
}

// ---------------------------------------------------------------------------
// fp16 GEMM tile body: D[row0:+128, n0:+128] = A @ B^T (+bias).
// BK=32, 3-stage cp.async.  kz = split-K column offset.
// EPI 0: attn (gc<1024 -> zh fp16, else v fp32)
// EPI 1: fp32 out + bias
// EPI 2: fp16 zh + per-n-block row-max partials (nx = n-block index)
// ---------------------------------------------------------------------------
template<int EPI, int KB, int KLD, int ALD, int NOUT>
__device__ __forceinline__ void gemm_tile(
    const __half* __restrict__ Ah, const __half* __restrict__ B,
    const float* __restrict__ bias, float* __restrict__ outf,
    __half* __restrict__ outh, float* __restrict__ pmax,
    int row0, int n0, int kz, int nx, char* smem)
{
    constexpr int BK     = 32;
    constexpr int STAGES = 3;
    constexpr int KT     = KB / BK;
    constexpr int LDS    = BK + 8;
    constexpr int ROWB   = LDS * 2;
    constexpr int OFF_B  = 128 * ROWB;
    constexpr int STG    = 256 * ROWB;             // 20480 B / stage
    constexpr int NI     = 4;

    const uint32_t sA = smem_u32(smem);
    const int tid  = threadIdx.x;
    const int wid  = tid >> 5, lane = tid & 31;
    const int wm   = wid >> 2, wn = wid & 3;

    __syncthreads();                               // protect smem reuse

    float acc[4][NI][4];
    #pragma unroll
    for (int mi = 0; mi < 4; mi++)
        #pragma unroll
        for (int ni = 0; ni < NI; ni++)
            #pragma unroll
            for (int r = 0; r < 4; r++) acc[mi][ni][r] = 0.0f;

    auto load_tiles = [&](int kt, int stage) {
        if (kt >= KT) return;
        const int chunk = tid & 3;
        const int kg    = kz + kt * BK + chunk * 8;
        const uint32_t stg = sA + stage * STG;
        #pragma unroll
        for (int p = 0; p < 2; p++) {
            const int row = (tid >> 2) + p * 64;
            const uint32_t so = (uint32_t)(row * LDS + chunk * 8) * 2;
            cp16(stg + so, Ah + (size_t)(row0 + row) * ALD + kg);
            cp16(stg + OFF_B + so, B + ((size_t)(n0 + row) * KLD + kg));
        }
    };

    #pragma unroll
    for (int s = 0; s < STAGES - 1; s++) { load_tiles(s, s); CP_COMMIT(); }

    for (int kt = 0; kt < KT; kt++) {
        CP_WAIT1();
        __syncthreads();
        load_tiles(kt + STAGES - 1, (kt + STAGES - 1) % STAGES);
        CP_COMMIT();

        const uint32_t stg = sA + (kt % STAGES) * STG;
        #pragma unroll
        for (int ks = 0; ks < 2; ks++) {
            const uint32_t aoff = (uint32_t)(ks * 16 + (lane >> 4) * 8) * 2;
            const uint32_t boff = (uint32_t)(ks * 16 + ((lane >> 3) & 1) * 8) * 2;
            uint32_t bfH[NI][2];
            #pragma unroll
            for (int ni = 0; ni < NI; ni++)
                ldmB(bfH[ni], stg + OFF_B +
                     (uint32_t)((wn * 32 + ni * 8 + (lane & 7)) * LDS) * 2 + boff);
            uint32_t afH[4][4];
            #pragma unroll
            for (int mi = 0; mi < 4; mi++)
                ldmA(afH[mi], stg +
                     (uint32_t)((wm * 64 + mi * 16 + (lane & 15)) * LDS) * 2 + aoff);
            #pragma unroll
            for (int mi = 0; mi < 4; mi++)
                #pragma unroll
                for (int ni = 0; ni < NI; ni++)
                    mma16816(acc[mi][ni], afH[mi], bfH[ni]);
        }
    }
    CP_WAIT0();
    __syncthreads();

    // ---- epilogue ----
    float* pm = (float*)smem;
    float rmax[4][2];
    #pragma unroll
    for (int mi = 0; mi < 4; mi++) { rmax[mi][0] = 0.0f; rmax[mi][1] = 0.0f; }

    #pragma unroll
    for (int mi = 0; mi < 4; mi++) {
        const int R0 = row0 + wm * 64 + mi * 16 + (lane >> 2);
        const int R1 = R0 + 8;
        #pragma unroll
        for (int ni = 0; ni < NI; ni++) {
            const int gc = n0 + wn * 32 + ni * 8 + 2 * (lane & 3);
            const float b0 = bias[gc], b1 = bias[gc + 1];
            float v0 = acc[mi][ni][0] + b0, v1 = acc[mi][ni][1] + b1;
            float v2 = acc[mi][ni][2] + b0, v3 = acc[mi][ni][3] + b1;
            if (EPI == 0) {
                if (gc < Cc) {
                    *(uint32_t*)&outh[(size_t)R0 * Cc + gc] = roundH2(v0, v1);
                    *(uint32_t*)&outh[(size_t)R1 * Cc + gc] = roundH2(v2, v3);
                } else {
                    *(float2*)&outf[(size_t)R0 * Cc + gc - Cc] = make_float2(v0, v1);
                    *(float2*)&outf[(size_t)R1 * Cc + gc - Cc] = make_float2(v2, v3);
                }
            } else if (EPI == 1) {
                *(float2*)&outf[(size_t)R0 * NOUT + gc] = make_float2(v0, v1);
                *(float2*)&outf[(size_t)R1 * NOUT + gc] = make_float2(v2, v3);
            } else {
                *(uint32_t*)&outh[(size_t)R0 * NOUT + gc] = roundH2(v0, v1);
                *(uint32_t*)&outh[(size_t)R1 * NOUT + gc] = roundH2(v2, v3);
                rmax[mi][0] = fmaxf(rmax[mi][0], fmaxf(fabsf(v0), fabsf(v1)));
                rmax[mi][1] = fmaxf(rmax[mi][1], fmaxf(fabsf(v2), fabsf(v3)));
            }
        }
    }

    if (EPI == 2) {
        #pragma unroll
        for (int mi = 0; mi < 4; mi++) {
            float m0 = rmax[mi][0], m1 = rmax[mi][1];
            #pragma unroll
            for (int off = 1; off < 4; off <<= 1) {
                m0 = fmaxf(m0, __shfl_xor_sync(0xffffffff, m0, off));
                m1 = fmaxf(m1, __shfl_xor_sync(0xffffffff, m1, off));
            }
            if ((lane & 3) == 0) {
                int lr = wm * 64 + mi * 16 + (lane >> 2);
                pm[lr * 4 + wn]       = m0;
                pm[(lr + 8) * 4 + wn] = m1;
            }
        }
        __syncthreads();
        if (tid < 128) {
            float m = fmaxf(fmaxf(pm[tid * 4], pm[tid * 4 + 1]),
                            fmaxf(pm[tid * 4 + 2], pm[tid * 4 + 3]));
            pmax[(size_t)nx * MM + row0 + tid] = m;
        }
    }
}

// ---------------------------------------------------------------------------
// Standalone GEMM wrapper (attn, proj)
// ---------------------------------------------------------------------------
template<int EPI, int KB, int KLD, int ALD, int NOUT>
__global__ __launch_bounds__(256, 2)
void mma_gemm(const __half* __restrict__ Ah, const __half* __restrict__ B,
              const float* __restrict__ bias, float* __restrict__ outf,
              __half* __restrict__ outh, float* __restrict__ pmax)
{
    extern __shared__ __align__(128) char smem[];
    gemm_tile<EPI, KB, KLD, ALD, NOUT>(Ah, B, bias, outf, outh, pmax,
                                       blockIdx.y * 128, blockIdx.x * 128,
                                       0, blockIdx.x, smem);
}

// ---------------------------------------------------------------------------
// Fused scan iteration: P0 rinv precompute, P1 freq split-K GEMM, barrier,
// P2 combine (shift + sincos), barrier, P3 out GEMM (4 tiles per CTA).
// Grid MUST be 256 CTAs (co-resident at 2 CTAs/SM on 148 SMs).
// ---------------------------------------------------------------------------
__global__ __launch_bounds__(256, 2)
void scan_iter_k(__half* __restrict__ zh,
                 const __half* __restrict__ fW, const __half* __restrict__ oW,
                 const float* __restrict__ out_b, const float* __restrict__ zerob,
                 float* __restrict__ u, __half* __restrict__ sch,
                 float* __restrict__ pmax, float* __restrict__ rinvg,
                 const float* __restrict__ c1, const float* __restrict__ freq_b,
                 int nShift, int iter)
{
    extern __shared__ __align__(128) char smem[];
    const int cta = blockIdx.x;
    const int tid = threadIdx.x;

    // P0: per-row rinv from previous iteration's pmax partials
    {
        int gt = cta * 256 + tid;
        if (gt < MM) rinvg[gt] = (iter == 0) ? 1.0f : get_rinv(pmax, gt);
    }

    // P1: freq GEMM, split-K x2 (cta parity), partial U buffers
    {
        int ky = cta & 1, rb = cta >> 1;
        gemm_tile<1, 512, 1024, 1024, 128>(
            zh, fW, zerob, u + (size_t)ky * MM * 128, nullptr, nullptr,
            rb * 128, 0, ky * 512, 0, smem);
    }
    grid_sync(gridDim.x);

    // P2: combine — sum partials, rinv scales, shift, sincos -> fp16 sc
    {
        const float* U2 = u + (size_t)MM * 128;
        #pragma unroll
        for (int i = 0; i < 16; i++) {
            int idx = i * 65536 + cta * 256 + tid;
            int row = idx >> 6, n = idx & 63;
            int t = row & (Tt - 1);
            size_t i2 = (size_t)row * 128 + 64 + n;
            float u2v = (u[i2] + U2[i2]) * rinvg[row];
            float u1v;
            if (t >= nShift) {
                int rp = row - nShift;
                size_t i1 = (size_t)rp * 128 + n;
                u1v = (u[i1] + U2[i1]) * rinvg[rp];
            } else {
                u1v = c1[n];
            }
            float f = u1v + u2v + freq_b[n];
            float s, c;
            sincosf(f, &s, &c);
            sch[(size_t)row * 128 + n]      = __float2half_rn(s);
            sch[(size_t)row * 128 + 64 + n] = __float2half_rn(c);
        }
    }
    grid_sync(gridDim.x);

    // P3: out GEMM, 4 tiles per CTA (1024 tiles exactly)
    #pragma unroll 1
    for (int t4 = 0; t4 < 4; t4++) {
        int tile = cta * 4 + t4;
        int nx = tile & 7, my = tile >> 3;
        gemm_tile<2, 128, 128, 128, 1024>(
            sch, oW, out_b, nullptr, zh, pmax,
            my * 128, nx * 128, 0, nx, smem);
    }
}

// ---------------------------------------------------------------------------
// Prep kernels
// ---------------------------------------------------------------------------
__global__ void cvt_k(const float* __restrict__ s, __half* __restrict__ h, int n)
{
    for (int i = blockIdx.x * blockDim.x + threadIdx.x; i < n;
         i += gridDim.x * blockDim.x)
        h[i] = __float2half_rn(s[i]);
}
// All weight transposes + c1 in one kernel (block-range partitioned)
__global__ void prep_w(const float* __restrict__ attn_W,
                       const float* __restrict__ freq_W,
                       const float* __restrict__ out_W,
                       const float* __restrict__ proj_W,
                       const float* __restrict__ identity,
                       __half* __restrict__ aW, __half* __restrict__ fW,
                       __half* __restrict__ oW, __half* __restrict__ pW,
                       float* __restrict__ c1)
{
    const int b = blockIdx.x, t = threadIdx.x;
    if (b < 2048) {            // attn_W [1024,2048] -> aW[n][k]
        #pragma unroll
        for (int j = 0; j < 4; j++) {
            int i = b * 1024 + j * 256 + t;
            int k = i >> 11, n = i & 2047;
            aW[(size_t)n * 1024 + k] = __float2half_rn(attn_W[i]);
        }
    } else if (b < 2304) {     // fW [128][1024] from freq_W [2048,64]
        #pragma unroll
        for (int j = 0; j < 2; j++) {
            int i = (b - 2048) * 512 + j * 256 + t;
            int n = i >> 10, k = i & 1023;
            float w = (n < 64) ? freq_W[(size_t)k * 64 + n]
                               : freq_W[(size_t)(1024 + k) * 64 + (n - 64)];
            fW[i] = __float2half_rn(w);
        }
    } else if (b < 2560) {     // out_W [128,1024] -> oW[n][k]
        #pragma unroll
        for (int j = 0; j < 2; j++) {
            int i = (b - 2304) * 512 + j * 256 + t;
            int k = i >> 10, n = i & 1023;
            oW[(size_t)n * 128 + k] = __float2half_rn(out_W[i]);
        }
    } else if (b < 3584) {     // proj_W [1024,1024] -> pW[n][k]
        #pragma unroll
        for (int j = 0; j < 4; j++) {
            int i = (b - 2560) * 1024 + j * 256 + t;
            int k = i >> 10, n = i & 1023;
            pW[(size_t)n * 1024 + k] = __float2half_rn(proj_W[i]);
        }
    } else {                   // c1[n] = identity @ freq_W[:, n]
        __shared__ float red[256];
        int n = b - 3584;
        float s = 0.0f;
        for (int k = t; k < 1024; k += 256)
            s += identity[k] * freq_W[(size_t)k * 64 + n];
        red[t] = s;
        __syncthreads();
        for (int o = 128; o > 0; o >>= 1) {
            if (t < o) red[t] += red[t + o];
            __syncthreads();
        }
        if (t == 0) c1[n] = red[0];
    }
}
// p = zh*rinv*v rounded to fp16 (proj A)
__global__ __launch_bounds__(256)
void mulround_k(const __half* __restrict__ zh, const float* __restrict__ pmax,
                const float* __restrict__ v, __half* __restrict__ ph)
{
    int wid = threadIdx.x >> 5, lane = threadIdx.x & 31;
    int r = blockIdx.x * 8 + wid;
    float rinv = get_rinv(pmax, r);
    #pragma unroll
    for (int j = 0; j < 8; j++) {
        int c = j * 128 + lane * 4;
        size_t b = (size_t)r * Cc + c;
        uint2 hw = *(const uint2*)&zh[b];
        float4 vv = *(const float4*)&v[b];
        float2 f0 = __half22float2(*(__half2*)&hw.x);
        float2 f1 = __half22float2(*(__half2*)&hw.y);
        uint2 o;
        o.x = roundH2(f0.x * rinv * vv.x, f0.y * rinv * vv.y);
        o.y = roundH2(f1.x * rinv * vv.z, f1.y * rinv * vv.w);
        *(uint2*)&ph[b] = o;
    }
}

// ---------------------------------------------------------------------------
extern "C" void kernel_launch(void* const* d_in, const int* in_sizes, int n_in,
                              void* d_out, int out_size)
{
    (void)in_sizes; (void)n_in; (void)out_size;
    const float* x        = (const float*)d_in[0];
    const float* attn_W   = (const float*)d_in[1];
    const float* attn_b   = (const float*)d_in[2];
    const float* freq_W   = (const float*)d_in[3];
    const float* freq_b   = (const float*)d_in[4];
    const float* out_W    = (const float*)d_in[5];
    const float* out_b    = (const float*)d_in[6];
    const float* proj_W   = (const float*)d_in[7];
    const float* proj_b   = (const float*)d_in[8];
    const float* identity = (const float*)d_in[9];

    __half *xh, *zh, *sch, *aW, *fW, *oW, *pW;
    float *v, *u, *pmax, *rinvg, *c1, *zerob;
    cudaGetSymbolAddress((void**)&xh,  g_xh);
    cudaGetSymbolAddress((void**)&zh,  g_zh);
    cudaGetSymbolAddress((void**)&v,   g_v);   cudaGetSymbolAddress((void**)&u,   g_u);
    cudaGetSymbolAddress((void**)&sch, g_sch);
    cudaGetSymbolAddress((void**)&pmax,g_pmax);cudaGetSymbolAddress((void**)&rinvg,g_rinv);
    cudaGetSymbolAddress((void**)&c1,  g_c1);  cudaGetSymbolAddress((void**)&zerob, g_zero);
    cudaGetSymbolAddress((void**)&aW,  g_aW);  cudaGetSymbolAddress((void**)&fW,  g_fW);
    cudaGetSymbolAddress((void**)&oW,  g_oW);  cudaGetSymbolAddress((void**)&pW,  g_pW);

    const int SMB = 3 * 256 * 80;   // 61440
    cudaFuncSetAttribute(mma_gemm<0, 1024, 1024, 1024, 2048>,
                         cudaFuncAttributeMaxDynamicSharedMemorySize, SMB);
    cudaFuncSetAttribute(mma_gemm<1, 1024, 1024, 1024, 1024>,
                         cudaFuncAttributeMaxDynamicSharedMemorySize, SMB);
    cudaFuncSetAttribute(scan_iter_k,
                         cudaFuncAttributeMaxDynamicSharedMemorySize, SMB);

    // prep
    cvt_k<<<8192, 256>>>(x, xh, MM * Cc);
    prep_w<<<3648, 256>>>(attn_W, freq_W, out_W, proj_W, identity,
                          aW, fW, oW, pW, c1);

    // attn: qv = x @ attn_W + attn_b -> q (zh fp16) | v (fp32)
    mma_gemm<0, 1024, 1024, 1024, 2048><<<dim3(16, 128), 256, SMB>>>(
        xh, aW, attn_b, v, zh, nullptr);

    // log-scan: one fused persistent kernel per iteration
    int iter = 0;
    for (int n = 1; n < Tt; n <<= 1, iter++)
        scan_iter_k<<<256, 256, SMB>>>(zh, fW, oW, out_b, zerob, u, sch,
                                       pmax, rinvg, c1, freq_b, n, iter);

    // proj: out = (mmnorm(z) * v) @ proj_W + proj_b
    mulround_k<<<MM / 8, 256>>>(zh, pmax, v, xh);
    mma_gemm<1, 1024, 1024, 1024, 1024><<<dim3(8, 128), 256, SMB>>>(
        xh, pW, proj_b, (float*)d_out, nullptr, nullptr);
}

// round 15
// speedup vs baseline: 1.1963x; 1.1963x over previous
#include <cuda_runtime.h>
#include <cuda_fp16.h>
#include <math.h>
#include <stdint.h>

#define MM   16384
#define Cc   1024
#define Tt   2048
#define EPSV 1e-6f

// ---------------------------------------------------------------------------
// Scratch (__device__ globals; no allocation allowed)
// ---------------------------------------------------------------------------
__device__ __half g_xh[MM * Cc];                  // x fp16; reused for q*v
__device__ __half g_zh[MM * Cc];                  // scan state (unnormalized z)
__device__ float  g_v [MM * Cc];
__device__ float  g_u [MM * 128];                 // U buffer
__device__ __half g_sch[MM * 128];
__device__ float  g_pmax[8 * MM];
__device__ float  g_c1[64];
__device__ float  g_cb[128];
__device__ float  g_zero[2048];                   // zero bias (static init 0)
__device__ __half g_aW[2048 * 1024];              // attn_W^T  [N][K]
__device__ __half g_fW[128 * 1024];               // [W1|W2]^T [N][K] (U0 only)
__device__ __half g_oW[1024 * 128];               // out_W^T   [N][K]
__device__ __half g_pW[1024 * 1024];              // proj_W^T  [N][K]
__device__ __half g_Wc[128 * 128];                // (out_W@Fcat)^T [N][K]

// ---------------------------------------------------------------------------
__device__ __forceinline__ uint32_t smem_u32(const void* p) {
    uint32_t a;
    asm("{ .reg .u64 t; cvta.to.shared.u64 t, %1; cvt.u32.u64 %0, t; }"
        : "=r"(a) : "l"(p));
    return a;
}
__device__ __forceinline__ void cp16(uint32_t dst, const void* src) {
    asm volatile("cp.async.cg.shared.global [%0], [%1], 16;"
                 :: "r"(dst), "l"(src));
}
#define CP_COMMIT() asm volatile("cp.async.commit_group;")
#define CP_WAIT1()  asm volatile("cp.async.wait_group 1;")
#define CP_WAIT0()  asm volatile("cp.async.wait_group 0;")

__device__ __forceinline__ void ldmA(uint32_t* a, uint32_t addr) {
    asm volatile("ldmatrix.sync.aligned.m8n8.x4.shared.b16 {%0,%1,%2,%3}, [%4];"
                 : "=r"(a[0]), "=r"(a[1]), "=r"(a[2]), "=r"(a[3]) : "r"(addr));
}
__device__ __forceinline__ void ldmB(uint32_t* b, uint32_t addr) {
    asm volatile("ldmatrix.sync.aligned.m8n8.x2.shared.b16 {%0,%1}, [%2];"
                 : "=r"(b[0]), "=r"(b[1]) : "r"(addr));
}
__device__ __forceinline__ void mma16816(float* c, const uint32_t* a,
                                         const uint32_t* b) {
    asm volatile("mma.sync.aligned.m16n8k16.row.col.f32.f16.f16.f32 "
                 "{%0,%1,%2,%3}, {%4,%5,%6,%7}, {%8,%9}, {%0,%1,%2,%3};"
                 : "+f"(c[0]), "+f"(c[1]), "+f"(c[2]), "+f"(c[3])
                 : "r"(a[0]), "r"(a[1]), "r"(a[2]), "r"(a[3]),
                   "r"(b[0]), "r"(b[1]));
}
__device__ __forceinline__ uint32_t roundH2(float a, float b) {
    __half2 hp = __halves2half2(__float2half_rn(a), __float2half_rn(b));
    return *(uint32_t*)&hp;
}
__device__ __forceinline__ float get_rinv(const float* pmax, int r) {
    float m = 0.0f;
    #pragma unroll
    for (int j = 0; j < 8; j++) m = fmaxf(m, pmax[j * MM + r]);
    return 1.0f / (m + EPSV);
}

// ---------------------------------------------------------------------------
// fp16 GEMM tile body: D[row0:+128, n0:+128] = A @ B^T (+bias).
// BK=32, 3-stage cp.async.
// EPI 0: attn (gc<1024 -> zh fp16, else v fp32)
// EPI 1: fp32 out + bias
// EPI 2: fp16 zh + per-n-block row-max partials (nx = n-block index)
// ---------------------------------------------------------------------------
template<int EPI, int KB, int KLD, int ALD, int NOUT>
__device__ __forceinline__ void gemm_tile(
    const __half* __restrict__ Ah, const __half* __restrict__ B,
    const float* __restrict__ bias, float* __restrict__ outf,
    __half* __restrict__ outh, float* __restrict__ pmax,
    int row0, int n0, int nx, char* smem)
{
    constexpr int BK     = 32;
    constexpr int STAGES = 3;
    constexpr int KT     = KB / BK;
    constexpr int LDS    = BK + 8;
    constexpr int ROWB   = LDS * 2;
    constexpr int OFF_B  = 128 * ROWB;
    constexpr int STG    = 256 * ROWB;             // 20480 B / stage
    constexpr int NI     = 4;

    const uint32_t sA = smem_u32(smem);
    const int tid  = threadIdx.x;
    const int wid  = tid >> 5, lane = tid & 31;
    const int wm   = wid >> 2, wn = wid & 3;

    float acc[4][NI][4];
    #pragma unroll
    for (int mi = 0; mi < 4; mi++)
        #pragma unroll
        for (int ni = 0; ni < NI; ni++)
            #pragma unroll
            for (int r = 0; r < 4; r++) acc[mi][ni][r] = 0.0f;

    auto load_tiles = [&](int kt, int stage) {
        if (kt >= KT) return;
        const int chunk = tid & 3;
        const int kg    = kt * BK + chunk * 8;
        const uint32_t stg = sA + stage * STG;
        #pragma unroll
        for (int p = 0; p < 2; p++) {
            const int row = (tid >> 2) + p * 64;
            const uint32_t so = (uint32_t)(row * LDS + chunk * 8) * 2;
            cp16(stg + so, Ah + (size_t)(row0 + row) * ALD + kg);
            cp16(stg + OFF_B + so, B + ((size_t)(n0 + row) * KLD + kg));
        }
    };

    #pragma unroll
    for (int s = 0; s < STAGES - 1; s++) { load_tiles(s, s); CP_COMMIT(); }

    for (int kt = 0; kt < KT; kt++) {
        CP_WAIT1();
        __syncthreads();
        load_tiles(kt + STAGES - 1, (kt + STAGES - 1) % STAGES);
        CP_COMMIT();

        const uint32_t stg = sA + (kt % STAGES) * STG;
        #pragma unroll
        for (int ks = 0; ks < 2; ks++) {
            const uint32_t aoff = (uint32_t)(ks * 16 + (lane >> 4) * 8) * 2;
            const uint32_t boff = (uint32_t)(ks * 16 + ((lane >> 3) & 1) * 8) * 2;
            uint32_t bfH[NI][2];
            #pragma unroll
            for (int ni = 0; ni < NI; ni++)
                ldmB(bfH[ni], stg + OFF_B +
                     (uint32_t)((wn * 32 + ni * 8 + (lane & 7)) * LDS) * 2 + boff);
            uint32_t afH[4][4];
            #pragma unroll
            for (int mi = 0; mi < 4; mi++)
                ldmA(afH[mi], stg +
                     (uint32_t)((wm * 64 + mi * 16 + (lane & 15)) * LDS) * 2 + aoff);
            #pragma unroll
            for (int mi = 0; mi < 4; mi++)
                #pragma unroll
                for (int ni = 0; ni < NI; ni++)
                    mma16816(acc[mi][ni], afH[mi], bfH[ni]);
        }
    }
    CP_WAIT0();
    __syncthreads();

    // ---- epilogue ----
    float* pm = (float*)smem;
    float rmax[4][2];
    #pragma unroll
    for (int mi = 0; mi < 4; mi++) { rmax[mi][0] = 0.0f; rmax[mi][1] = 0.0f; }

    #pragma unroll
    for (int mi = 0; mi < 4; mi++) {
        const int R0 = row0 + wm * 64 + mi * 16 + (lane >> 2);
        const int R1 = R0 + 8;
        #pragma unroll
        for (int ni = 0; ni < NI; ni++) {
            const int gc = n0 + wn * 32 + ni * 8 + 2 * (lane & 3);
            const float b0 = bias[gc], b1 = bias[gc + 1];
            float v0 = acc[mi][ni][0] + b0, v1 = acc[mi][ni][1] + b1;
            float v2 = acc[mi][ni][2] + b0, v3 = acc[mi][ni][3] + b1;
            if (EPI == 0) {
                if (gc < Cc) {
                    *(uint32_t*)&outh[(size_t)R0 * Cc + gc] = roundH2(v0, v1);
                    *(uint32_t*)&outh[(size_t)R1 * Cc + gc] = roundH2(v2, v3);
                } else {
                    *(float2*)&outf[(size_t)R0 * Cc + gc - Cc] = make_float2(v0, v1);
                    *(float2*)&outf[(size_t)R1 * Cc + gc - Cc] = make_float2(v2, v3);
                }
            } else if (EPI == 1) {
                *(float2*)&outf[(size_t)R0 * NOUT + gc] = make_float2(v0, v1);
                *(float2*)&outf[(size_t)R1 * NOUT + gc] = make_float2(v2, v3);
            } else {
                *(uint32_t*)&outh[(size_t)R0 * NOUT + gc] = roundH2(v0, v1);
                *(uint32_t*)&outh[(size_t)R1 * NOUT + gc] = roundH2(v2, v3);
                rmax[mi][0] = fmaxf(rmax[mi][0], fmaxf(fabsf(v0), fabsf(v1)));
                rmax[mi][1] = fmaxf(rmax[mi][1], fmaxf(fabsf(v2), fabsf(v3)));
            }
        }
    }

    if (EPI == 2) {
        #pragma unroll
        for (int mi = 0; mi < 4; mi++) {
            float m0 = rmax[mi][0], m1 = rmax[mi][1];
            #pragma unroll
            for (int off = 1; off < 4; off <<= 1) {
                m0 = fmaxf(m0, __shfl_xor_sync(0xffffffff, m0, off));
                m1 = fmaxf(m1, __shfl_xor_sync(0xffffffff, m1, off));
            }
            if ((lane & 3) == 0) {
                int lr = wm * 64 + mi * 16 + (lane >> 2);
                pm[lr * 4 + wn]       = m0;
                pm[(lr + 8) * 4 + wn] = m1;
            }
        }
        __syncthreads();
        if (tid < 128) {
            float m = fmaxf(fmaxf(pm[tid * 4], pm[tid * 4 + 1]),
                            fmaxf(pm[tid * 4 + 2], pm[tid * 4 + 3]));
            pmax[(size_t)nx * MM + row0 + tid] = m;
        }
    }
}

// ---------------------------------------------------------------------------
// Standalone GEMM wrapper (attn, proj, U0)
// ---------------------------------------------------------------------------
template<int EPI, int KB, int KLD, int ALD, int NOUT>
__global__ __launch_bounds__(256, 2)
void mma_gemm(const __half* __restrict__ Ah, const __half* __restrict__ B,
              const float* __restrict__ bias, float* __restrict__ outf,
              __half* __restrict__ outh, float* __restrict__ pmax)
{
    extern __shared__ __align__(128) char smem[];
    gemm_tile<EPI, KB, KLD, ALD, NOUT>(Ah, B, bias, outf, outh, pmax,
                                       blockIdx.y * 128, blockIdx.x * 128,
                                       blockIdx.x, smem);
}

// ---------------------------------------------------------------------------
// Fused scan GEMM: nx<8 -> z' = sc @ out_W^T (fp16 + pmax partials);
//                  nx==8 -> U' = sc @ Wc^T + cb (fp32, for next combine)
// ---------------------------------------------------------------------------
__global__ __launch_bounds__(256, 2)
void outu_k(const __half* __restrict__ sch, const __half* __restrict__ oW,
            const __half* __restrict__ Wc,
            const float* __restrict__ out_b, const float* __restrict__ cb,
            __half* __restrict__ zh, float* __restrict__ u,
            float* __restrict__ pmax)
{
    extern __shared__ __align__(128) char smem[];
    const int nx = blockIdx.x, my = blockIdx.y;
    if (nx < 8)
        gemm_tile<2, 128, 128, 128, 1024>(sch, oW, out_b, nullptr, zh, pmax,
                                          my * 128, nx * 128, nx, smem);
    else
        gemm_tile<1, 128, 128, 128, 128>(sch, Wc, cb, u, nullptr, nullptr,
                                         my * 128, 0, 0, smem);
}

// ---------------------------------------------------------------------------
// combine: f = rinv[t-n]*U1[t-n] (or c1) + rinv[t]*U2[t] + freq_b
//          sc = [sin f, cos f] fp16.  rinv staged via smem (8 loads / block).
// ---------------------------------------------------------------------------
__global__ __launch_bounds__(256)
void combine_k(const float* __restrict__ U, const float* __restrict__ pmax,
               const float* __restrict__ c1, const float* __restrict__ freq_b,
               __half* __restrict__ sch, int nShift)
{
    __shared__ float rv[4], rvp[4];
    const int tid  = threadIdx.x;
    const int rloc = tid >> 6, n = tid & 63;
    const int row  = blockIdx.x * 4 + rloc;
    const int t    = row & (Tt - 1);

    if (tid < 8) {
        int sl = tid & 3;
        int r  = blockIdx.x * 4 + sl;
        if (tid < 4) {
            rv[sl] = pmax ? get_rinv(pmax, r) : 1.0f;
        } else {
            int tt = r & (Tt - 1);
            rvp[sl] = (tt >= nShift)
                      ? (pmax ? get_rinv(pmax, r - nShift) : 1.0f) : 0.0f;
        }
    }
    __syncthreads();

    float u2 = U[(size_t)row * 128 + 64 + n] * rv[rloc];
    float u1 = (t >= nShift)
               ? U[(size_t)(row - nShift) * 128 + n] * rvp[rloc]
               : c1[n];
    float f = u1 + u2 + freq_b[n];
    float s, c;
    sincosf(f, &s, &c);
    sch[(size_t)row * 128 + n]      = __float2half_rn(s);
    sch[(size_t)row * 128 + 64 + n] = __float2half_rn(c);
}

// ---------------------------------------------------------------------------
// Prep kernels
// ---------------------------------------------------------------------------
__global__ void cvt_k(const float* __restrict__ s, __half* __restrict__ h, int n)
{
    for (int i = blockIdx.x * blockDim.x + threadIdx.x; i < n;
         i += gridDim.x * blockDim.x)
        h[i] = __float2half_rn(s[i]);
}
// All weight transposes + c1 + Wc + cb in one kernel (block-range partitioned)
__global__ void prep_w(const float* __restrict__ attn_W,
                       const float* __restrict__ freq_W,
                       const float* __restrict__ out_W,
                       const float* __restrict__ proj_W,
                       const float* __restrict__ identity,
                       const float* __restrict__ out_b,
                       __half* __restrict__ aW, __half* __restrict__ fW,
                       __half* __restrict__ oW, __half* __restrict__ pW,
                       __half* __restrict__ Wc,
                       float* __restrict__ c1, float* __restrict__ cb)
{
    const int b = blockIdx.x, t = threadIdx.x;
    if (b < 2048) {            // attn_W [1024,2048] -> aW[n][k]
        #pragma unroll
        for (int j = 0; j < 4; j++) {
            int i = b * 1024 + j * 256 + t;
            int k = i >> 11, n = i & 2047;
            aW[(size_t)n * 1024 + k] = __float2half_rn(attn_W[i]);
        }
    } else if (b < 2304) {     // fW [128][1024] from freq_W [2048,64]
        #pragma unroll
        for (int j = 0; j < 2; j++) {
            int i = (b - 2048) * 512 + j * 256 + t;
            int n = i >> 10, k = i & 1023;
            float w = (n < 64) ? freq_W[(size_t)k * 64 + n]
                               : freq_W[(size_t)(1024 + k) * 64 + (n - 64)];
            fW[i] = __float2half_rn(w);
        }
    } else if (b < 2560) {     // out_W [128,1024] -> oW[n][k]
        #pragma unroll
        for (int j = 0; j < 2; j++) {
            int i = (b - 2304) * 512 + j * 256 + t;
            int k = i >> 10, n = i & 1023;
            oW[(size_t)n * 128 + k] = __float2half_rn(out_W[i]);
        }
    } else if (b < 3584) {     // proj_W [1024,1024] -> pW[n][k]
        #pragma unroll
        for (int j = 0; j < 4; j++) {
            int i = (b - 2560) * 1024 + j * 256 + t;
            int k = i >> 10, n = i & 1023;
            pW[(size_t)n * 1024 + k] = __float2half_rn(proj_W[i]);
        }
    } else if (b < 3648) {     // c1[n] = identity @ W1[:, n]
        __shared__ float red[256];
        int n = b - 3584;
        float s = 0.0f;
        for (int k = t; k < 1024; k += 256)
            s += identity[k] * freq_W[(size_t)k * 64 + n];
        red[t] = s;
        __syncthreads();
        for (int o = 128; o > 0; o >>= 1) {
            if (t < o) red[t] += red[t + o];
            __syncthreads();
        }
        if (t == 0) c1[n] = red[0];
    } else if (b < 5696) {     // Wc[n][k] = sum_j out_W[k,j] * Fcat[j,n]
        int bb = b - 3648;
        int n  = bb >> 4;
        int k  = (bb & 15) * 8 + (t >> 5);
        int lane = t & 31;
        float s = 0.0f;
        for (int j = lane; j < 1024; j += 32) {
            float fc = (n < 64) ? freq_W[(size_t)j * 64 + n]
                                : freq_W[(size_t)(1024 + j) * 64 + (n - 64)];
            s += out_W[(size_t)k * 1024 + j] * fc;
        }
        #pragma unroll
        for (int o = 16; o > 0; o >>= 1)
            s += __shfl_xor_sync(0xffffffff, s, o);
        if (lane == 0) Wc[(size_t)n * 128 + k] = __float2half_rn(s);
    } else {                   // cb[n] = out_b @ Fcat[:, n]
        __shared__ float red[256];
        int n = b - 5696;
        float s = 0.0f;
        for (int j = t; j < 1024; j += 256) {
            float fc = (n < 64) ? freq_W[(size_t)j * 64 + n]
                                : freq_W[(size_t)(1024 + j) * 64 + (n - 64)];
            s += out_b[j] * fc;
        }
        red[t] = s;
        __syncthreads();
        for (int o = 128; o > 0; o >>= 1) {
            if (t < o) red[t] += red[t + o];
            __syncthreads();
        }
        if (t == 0) cb[n] = red[0];
    }
}
// p = zh*rinv*v rounded to fp16 (proj A)
__global__ __launch_bounds__(256)
void mulround_k(const __half* __restrict__ zh, const float* __restrict__ pmax,
                const float* __restrict__ v, __half* __restrict__ ph)
{
    int wid = threadIdx.x >> 5, lane = threadIdx.x & 31;
    int r = blockIdx.x * 8 + wid;
    float rinv = get_rinv(pmax, r);
    #pragma unroll
    for (int j = 0; j < 8; j++) {
        int c = j * 128 + lane * 4;
        size_t b = (size_t)r * Cc + c;
        uint2 hw = *(const uint2*)&zh[b];
        float4 vv = *(const float4*)&v[b];
        float2 f0 = __half22float2(*(__half2*)&hw.x);
        float2 f1 = __half22float2(*(__half2*)&hw.y);
        uint2 o;
        o.x = roundH2(f0.x * rinv * vv.x, f0.y * rinv * vv.y);
        o.y = roundH2(f1.x * rinv * vv.z, f1.y * rinv * vv.w);
        *(uint2*)&ph[b] = o;
    }
}

// ---------------------------------------------------------------------------
extern "C" void kernel_launch(void* const* d_in, const int* in_sizes, int n_in,
                              void* d_out, int out_size)
{
    (void)in_sizes; (void)n_in; (void)out_size;
    const float* x        = (const float*)d_in[0];
    const float* attn_W   = (const float*)d_in[1];
    const float* attn_b   = (const float*)d_in[2];
    const float* freq_W   = (const float*)d_in[3];
    const float* freq_b   = (const float*)d_in[4];
    const float* out_W    = (const float*)d_in[5];
    const float* out_b    = (const float*)d_in[6];
    const float* proj_W   = (const float*)d_in[7];
    const float* proj_b   = (const float*)d_in[8];
    const float* identity = (const float*)d_in[9];

    __half *xh, *zh, *sch, *aW, *fW, *oW, *pW, *Wc;
    float *v, *u, *pmax, *c1, *cb, *zerob;
    cudaGetSymbolAddress((void**)&xh,  g_xh);
    cudaGetSymbolAddress((void**)&zh,  g_zh);
    cudaGetSymbolAddress((void**)&v,   g_v);   cudaGetSymbolAddress((void**)&u,   g_u);
    cudaGetSymbolAddress((void**)&sch, g_sch);
    cudaGetSymbolAddress((void**)&pmax,g_pmax);
    cudaGetSymbolAddress((void**)&c1,  g_c1);  cudaGetSymbolAddress((void**)&cb,  g_cb);
    cudaGetSymbolAddress((void**)&zerob, g_zero);
    cudaGetSymbolAddress((void**)&aW,  g_aW);  cudaGetSymbolAddress((void**)&fW,  g_fW);
    cudaGetSymbolAddress((void**)&oW,  g_oW);  cudaGetSymbolAddress((void**)&pW,  g_pW);
    cudaGetSymbolAddress((void**)&Wc,  g_Wc);

    const int SMB = 3 * 256 * 80;   // 61440
    cudaFuncSetAttribute(mma_gemm<0, 1024, 1024, 1024, 2048>,
                         cudaFuncAttributeMaxDynamicSharedMemorySize, SMB);
    cudaFuncSetAttribute(mma_gemm<1, 1024, 1024, 1024, 128>,
                         cudaFuncAttributeMaxDynamicSharedMemorySize, SMB);
    cudaFuncSetAttribute(mma_gemm<1, 1024, 1024, 1024, 1024>,
                         cudaFuncAttributeMaxDynamicSharedMemorySize, SMB);
    cudaFuncSetAttribute(outu_k,
                         cudaFuncAttributeMaxDynamicSharedMemorySize, SMB);

    // prep
    cvt_k<<<8192, 256>>>(x, xh, MM * Cc);
    prep_w<<<5824, 256>>>(attn_W, freq_W, out_W, proj_W, identity, out_b,
                          aW, fW, oW, pW, Wc, c1, cb);

    // attn: qv = x @ attn_W + attn_b -> z0 (zh fp16) | v (fp32)
    mma_gemm<0, 1024, 1024, 1024, 2048><<<dim3(16, 128), 256, SMB>>>(
        xh, aW, attn_b, v, zh, nullptr);

    // U0 = z0 @ Fcat (one-time full freq GEMM)
    mma_gemm<1, 1024, 1024, 1024, 128><<<dim3(1, 128), 256, SMB>>>(
        zh, fW, zerob, u, nullptr, nullptr);

    // log-scan: combine + fused (out GEMM | U GEMM) per iteration
    int iter = 0;
    for (int n = 1; n < Tt; n <<= 1, iter++) {
        combine_k<<<MM / 4, 256>>>(u, (iter == 0) ? nullptr : pmax,
                                   c1, freq_b, sch, n);
        int gx = (iter < 10) ? 9 : 8;   // last iteration: skip U tile
        outu_k<<<dim3(gx, 128), 256, SMB>>>(sch, oW, Wc, out_b, cb,
                                            zh, u, pmax);
    }

    // proj: out = (mmnorm(z) * v) @ proj_W + proj_b
    mulround_k<<<MM / 8, 256>>>(zh, pmax, v, xh);
    mma_gemm<1, 1024, 1024, 1024, 1024><<<dim3(8, 128), 256, SMB>>>(
        xh, pW, proj_b, (float*)d_out, nullptr, nullptr);
}

// round 16
// speedup vs baseline: 1.3000x; 1.0867x over previous
#include <cuda_runtime.h>
#include <cuda_fp16.h>
#include <math.h>
#include <stdint.h>

#define MM   16384
#define Cc   1024
#define Tt   2048
#define EPSV 1e-6f

// ---------------------------------------------------------------------------
// Scratch (__device__ globals; no allocation allowed)
// ---------------------------------------------------------------------------
__device__ __half g_xh[MM * Cc];                  // x fp16; reused for q*v
__device__ __half g_zh[MM * Cc];                  // final-iteration z only
__device__ float  g_v [MM * Cc];
__device__ float  g_u [MM * 128];                 // U buffer
__device__ __half g_sch[MM * 128];
__device__ float  g_pmax[8 * MM];
__device__ float  g_c1[64];
__device__ float  g_cb[128];
__device__ float  g_zero[2048];                   // zero bias (static init 0)
__device__ __half g_aW[2048 * 1024];              // attn_W^T  [N][K]
__device__ __half g_fW[128 * 1024];               // [W1|W2]^T [N][K] (U0 only)
__device__ __half g_oW[1024 * 128];               // out_W^T   [N][K]
__device__ __half g_pW[1024 * 1024];              // proj_W^T  [N][K]
__device__ __half g_Wc[128 * 128];                // (out_W@Fcat)^T [N][K]

// ---------------------------------------------------------------------------
__device__ __forceinline__ uint32_t smem_u32(const void* p) {
    uint32_t a;
    asm("{ .reg .u64 t; cvta.to.shared.u64 t, %1; cvt.u32.u64 %0, t; }"
        : "=r"(a) : "l"(p));
    return a;
}
__device__ __forceinline__ void cp16(uint32_t dst, const void* src) {
    asm volatile("cp.async.cg.shared.global [%0], [%1], 16;"
                 :: "r"(dst), "l"(src));
}
#define CP_COMMIT() asm volatile("cp.async.commit_group;")
#define CP_WAIT1()  asm volatile("cp.async.wait_group 1;")
#define CP_WAIT0()  asm volatile("cp.async.wait_group 0;")

__device__ __forceinline__ void ldmA(uint32_t* a, uint32_t addr) {
    asm volatile("ldmatrix.sync.aligned.m8n8.x4.shared.b16 {%0,%1,%2,%3}, [%4];"
                 : "=r"(a[0]), "=r"(a[1]), "=r"(a[2]), "=r"(a[3]) : "r"(addr));
}
__device__ __forceinline__ void ldmB(uint32_t* b, uint32_t addr) {
    asm volatile("ldmatrix.sync.aligned.m8n8.x2.shared.b16 {%0,%1}, [%2];"
                 : "=r"(b[0]), "=r"(b[1]) : "r"(addr));
}
__device__ __forceinline__ void mma16816(float* c, const uint32_t* a,
                                         const uint32_t* b) {
    asm volatile("mma.sync.aligned.m16n8k16.row.col.f32.f16.f16.f32 "
                 "{%0,%1,%2,%3}, {%4,%5,%6,%7}, {%8,%9}, {%0,%1,%2,%3};"
                 : "+f"(c[0]), "+f"(c[1]), "+f"(c[2]), "+f"(c[3])
                 : "r"(a[0]), "r"(a[1]), "r"(a[2]), "r"(a[3]),
                   "r"(b[0]), "r"(b[1]));
}
__device__ __forceinline__ uint32_t roundH2(float a, float b) {
    __half2 hp = __halves2half2(__float2half_rn(a), __float2half_rn(b));
    return *(uint32_t*)&hp;
}
__device__ __forceinline__ float get_rinv(const float* pmax, int r) {
    float m = 0.0f;
    #pragma unroll
    for (int j = 0; j < 8; j++) m = fmaxf(m, pmax[j * MM + r]);
    return 1.0f / (m + EPSV);
}

// ---------------------------------------------------------------------------
// fp16 GEMM tile body: D[row0:+128, n0:+128] = A @ B^T (+bias).
// BK=32, 3-stage cp.async.
// EPI 0: attn (gc<1024 -> zh fp16, else v fp32)
// EPI 1: fp32 out + bias
// EPI 2: fp16 zh + per-n-block row-max partials (nx = n-block index)
// EPI 3: row-max partials ONLY (dead-store-eliminated scan z-GEMM)
// ---------------------------------------------------------------------------
template<int EPI, int KB, int KLD, int ALD, int NOUT>
__device__ __forceinline__ void gemm_tile(
    const __half* __restrict__ Ah, const __half* __restrict__ B,
    const float* __restrict__ bias, float* __restrict__ outf,
    __half* __restrict__ outh, float* __restrict__ pmax,
    int row0, int n0, int nx, char* smem)
{
    constexpr int BK     = 32;
    constexpr int STAGES = 3;
    constexpr int KT     = KB / BK;
    constexpr int LDS    = BK + 8;
    constexpr int ROWB   = LDS * 2;
    constexpr int OFF_B  = 128 * ROWB;
    constexpr int STG    = 256 * ROWB;             // 20480 B / stage
    constexpr int NI     = 4;

    const uint32_t sA = smem_u32(smem);
    const int tid  = threadIdx.x;
    const int wid  = tid >> 5, lane = tid & 31;
    const int wm   = wid >> 2, wn = wid & 3;

    float acc[4][NI][4];
    #pragma unroll
    for (int mi = 0; mi < 4; mi++)
        #pragma unroll
        for (int ni = 0; ni < NI; ni++)
            #pragma unroll
            for (int r = 0; r < 4; r++) acc[mi][ni][r] = 0.0f;

    auto load_tiles = [&](int kt, int stage) {
        if (kt >= KT) return;
        const int chunk = tid & 3;
        const int kg    = kt * BK + chunk * 8;
        const uint32_t stg = sA + stage * STG;
        #pragma unroll
        for (int p = 0; p < 2; p++) {
            const int row = (tid >> 2) + p * 64;
            const uint32_t so = (uint32_t)(row * LDS + chunk * 8) * 2;
            cp16(stg + so, Ah + (size_t)(row0 + row) * ALD + kg);
            cp16(stg + OFF_B + so, B + ((size_t)(n0 + row) * KLD + kg));
        }
    };

    #pragma unroll
    for (int s = 0; s < STAGES - 1; s++) { load_tiles(s, s); CP_COMMIT(); }

    for (int kt = 0; kt < KT; kt++) {
        CP_WAIT1();
        __syncthreads();
        load_tiles(kt + STAGES - 1, (kt + STAGES - 1) % STAGES);
        CP_COMMIT();

        const uint32_t stg = sA + (kt % STAGES) * STG;
        #pragma unroll
        for (int ks = 0; ks < 2; ks++) {
            const uint32_t aoff = (uint32_t)(ks * 16 + (lane >> 4) * 8) * 2;
            const uint32_t boff = (uint32_t)(ks * 16 + ((lane >> 3) & 1) * 8) * 2;
            uint32_t bfH[NI][2];
            #pragma unroll
            for (int ni = 0; ni < NI; ni++)
                ldmB(bfH[ni], stg + OFF_B +
                     (uint32_t)((wn * 32 + ni * 8 + (lane & 7)) * LDS) * 2 + boff);
            uint32_t afH[4][4];
            #pragma unroll
            for (int mi = 0; mi < 4; mi++)
                ldmA(afH[mi], stg +
                     (uint32_t)((wm * 64 + mi * 16 + (lane & 15)) * LDS) * 2 + aoff);
            #pragma unroll
            for (int mi = 0; mi < 4; mi++)
                #pragma unroll
                for (int ni = 0; ni < NI; ni++)
                    mma16816(acc[mi][ni], afH[mi], bfH[ni]);
        }
    }
    CP_WAIT0();
    __syncthreads();

    // ---- epilogue ----
    float* pm = (float*)smem;
    float rmax[4][2];
    #pragma unroll
    for (int mi = 0; mi < 4; mi++) { rmax[mi][0] = 0.0f; rmax[mi][1] = 0.0f; }

    #pragma unroll
    for (int mi = 0; mi < 4; mi++) {
        const int R0 = row0 + wm * 64 + mi * 16 + (lane >> 2);
        const int R1 = R0 + 8;
        #pragma unroll
        for (int ni = 0; ni < NI; ni++) {
            const int gc = n0 + wn * 32 + ni * 8 + 2 * (lane & 3);
            const float b0 = bias[gc], b1 = bias[gc + 1];
            float v0 = acc[mi][ni][0] + b0, v1 = acc[mi][ni][1] + b1;
            float v2 = acc[mi][ni][2] + b0, v3 = acc[mi][ni][3] + b1;
            if (EPI == 0) {
                if (gc < Cc) {
                    *(uint32_t*)&outh[(size_t)R0 * Cc + gc] = roundH2(v0, v1);
                    *(uint32_t*)&outh[(size_t)R1 * Cc + gc] = roundH2(v2, v3);
                } else {
                    *(float2*)&outf[(size_t)R0 * Cc + gc - Cc] = make_float2(v0, v1);
                    *(float2*)&outf[(size_t)R1 * Cc + gc - Cc] = make_float2(v2, v3);
                }
            } else if (EPI == 1) {
                *(float2*)&outf[(size_t)R0 * NOUT + gc] = make_float2(v0, v1);
                *(float2*)&outf[(size_t)R1 * NOUT + gc] = make_float2(v2, v3);
            } else {
                if (EPI == 2) {
                    *(uint32_t*)&outh[(size_t)R0 * NOUT + gc] = roundH2(v0, v1);
                    *(uint32_t*)&outh[(size_t)R1 * NOUT + gc] = roundH2(v2, v3);
                }
                rmax[mi][0] = fmaxf(rmax[mi][0], fmaxf(fabsf(v0), fabsf(v1)));
                rmax[mi][1] = fmaxf(rmax[mi][1], fmaxf(fabsf(v2), fabsf(v3)));
            }
        }
    }

    if (EPI >= 2) {
        #pragma unroll
        for (int mi = 0; mi < 4; mi++) {
            float m0 = rmax[mi][0], m1 = rmax[mi][1];
            #pragma unroll
            for (int off = 1; off < 4; off <<= 1) {
                m0 = fmaxf(m0, __shfl_xor_sync(0xffffffff, m0, off));
                m1 = fmaxf(m1, __shfl_xor_sync(0xffffffff, m1, off));
            }
            if ((lane & 3) == 0) {
                int lr = wm * 64 + mi * 16 + (lane >> 2);
                pm[lr * 4 + wn]       = m0;
                pm[(lr + 8) * 4 + wn] = m1;
            }
        }
        __syncthreads();
        if (tid < 128) {
            float m = fmaxf(fmaxf(pm[tid * 4], pm[tid * 4 + 1]),
                            fmaxf(pm[tid * 4 + 2], pm[tid * 4 + 3]));
            pmax[(size_t)nx * MM + row0 + tid] = m;
        }
    }
}

// ---------------------------------------------------------------------------
// Standalone GEMM wrapper (attn, proj, U0)
// ---------------------------------------------------------------------------
template<int EPI, int KB, int KLD, int ALD, int NOUT>
__global__ __launch_bounds__(256, 2)
void mma_gemm(const __half* __restrict__ Ah, const __half* __restrict__ B,
              const float* __restrict__ bias, float* __restrict__ outf,
              __half* __restrict__ outh, float* __restrict__ pmax)
{
    extern __shared__ __align__(128) char smem[];
    gemm_tile<EPI, KB, KLD, ALD, NOUT>(Ah, B, bias, outf, outh, pmax,
                                       blockIdx.y * 128, blockIdx.x * 128,
                                       blockIdx.x, smem);
}

// ---------------------------------------------------------------------------
// Fused scan GEMM.
// nx<8  -> z-tile: WRITEZ=0: pmax partials only (z is dead until last iter);
//                  WRITEZ=1: fp16 zh + pmax partials (final iteration).
// nx==8 -> U' = sc @ Wc^T + cb (fp32, next combine input)
// ---------------------------------------------------------------------------
template<int WRITEZ>
__global__ __launch_bounds__(256, 2)
void outu_k(const __half* __restrict__ sch, const __half* __restrict__ oW,
            const __half* __restrict__ Wc,
            const float* __restrict__ out_b, const float* __restrict__ cb,
            __half* __restrict__ zh, float* __restrict__ u,
            float* __restrict__ pmax)
{
    extern __shared__ __align__(128) char smem[];
    const int nx = blockIdx.x, my = blockIdx.y;
    if (nx < 8) {
        if (WRITEZ)
            gemm_tile<2, 128, 128, 128, 1024>(sch, oW, out_b, nullptr, zh, pmax,
                                              my * 128, nx * 128, nx, smem);
        else
            gemm_tile<3, 128, 128, 128, 1024>(sch, oW, out_b, nullptr, zh, pmax,
                                              my * 128, nx * 128, nx, smem);
    } else {
        gemm_tile<1, 128, 128, 128, 128>(sch, Wc, cb, u, nullptr, nullptr,
                                         my * 128, 0, 0, smem);
    }
}

// ---------------------------------------------------------------------------
// combine: f = rinv[t-n]*U1[t-n] (or c1) + rinv[t]*U2[t] + freq_b
//          sc = [sin f, cos f] fp16.  rinv staged via smem (8 loads / block).
// ---------------------------------------------------------------------------
__global__ __launch_bounds__(256)
void combine_k(const float* __restrict__ U, const float* __restrict__ pmax,
               const float* __restrict__ c1, const float* __restrict__ freq_b,
               __half* __restrict__ sch, int nShift)
{
    __shared__ float rv[4], rvp[4];
    const int tid  = threadIdx.x;
    const int rloc = tid >> 6, n = tid & 63;
    const int row  = blockIdx.x * 4 + rloc;
    const int t    = row & (Tt - 1);

    if (tid < 8) {
        int sl = tid & 3;
        int r  = blockIdx.x * 4 + sl;
        if (tid < 4) {
            rv[sl] = pmax ? get_rinv(pmax, r) : 1.0f;
        } else {
            int tt = r & (Tt - 1);
            rvp[sl] = (tt >= nShift)
                      ? (pmax ? get_rinv(pmax, r - nShift) : 1.0f) : 0.0f;
        }
    }
    __syncthreads();

    float u2 = U[(size_t)row * 128 + 64 + n] * rv[rloc];
    float u1 = (t >= nShift)
               ? U[(size_t)(row - nShift) * 128 + n] * rvp[rloc]
               : c1[n];
    float f = u1 + u2 + freq_b[n];
    float s, c;
    sincosf(f, &s, &c);
    sch[(size_t)row * 128 + n]      = __float2half_rn(s);
    sch[(size_t)row * 128 + 64 + n] = __float2half_rn(c);
}

// ---------------------------------------------------------------------------
// Prep kernels
// ---------------------------------------------------------------------------
__global__ void cvt_k(const float* __restrict__ s, __half* __restrict__ h, int n)
{
    for (int i = blockIdx.x * blockDim.x + threadIdx.x; i < n;
         i += gridDim.x * blockDim.x)
        h[i] = __float2half_rn(s[i]);
}
// All weight transposes + c1 + Wc + cb in one kernel (block-range partitioned)
__global__ void prep_w(const float* __restrict__ attn_W,
                       const float* __restrict__ freq_W,
                       const float* __restrict__ out_W,
                       const float* __restrict__ proj_W,
                       const float* __restrict__ identity,
                       const float* __restrict__ out_b,
                       __half* __restrict__ aW, __half* __restrict__ fW,
                       __half* __restrict__ oW, __half* __restrict__ pW,
                       __half* __restrict__ Wc,
                       float* __restrict__ c1, float* __restrict__ cb)
{
    const int b = blockIdx.x, t = threadIdx.x;
    if (b < 2048) {            // attn_W [1024,2048] -> aW[n][k]
        #pragma unroll
        for (int j = 0; j < 4; j++) {
            int i = b * 1024 + j * 256 + t;
            int k = i >> 11, n = i & 2047;
            aW[(size_t)n * 1024 + k] = __float2half_rn(attn_W[i]);
        }
    } else if (b < 2304) {     // fW [128][1024] from freq_W [2048,64]
        #pragma unroll
        for (int j = 0; j < 2; j++) {
            int i = (b - 2048) * 512 + j * 256 + t;
            int n = i >> 10, k = i & 1023;
            float w = (n < 64) ? freq_W[(size_t)k * 64 + n]
                               : freq_W[(size_t)(1024 + k) * 64 + (n - 64)];
            fW[i] = __float2half_rn(w);
        }
    } else if (b < 2560) {     // out_W [128,1024] -> oW[n][k]
        #pragma unroll
        for (int j = 0; j < 2; j++) {
            int i = (b - 2304) * 512 + j * 256 + t;
            int k = i >> 10, n = i & 1023;
            oW[(size_t)n * 128 + k] = __float2half_rn(out_W[i]);
        }
    } else if (b < 3584) {     // proj_W [1024,1024] -> pW[n][k]
        #pragma unroll
        for (int j = 0; j < 4; j++) {
            int i = (b - 2560) * 1024 + j * 256 + t;
            int k = i >> 10, n = i & 1023;
            pW[(size_t)n * 1024 + k] = __float2half_rn(proj_W[i]);
        }
    } else if (b < 3648) {     // c1[n] = identity @ W1[:, n]
        __shared__ float red[256];
        int n = b - 3584;
        float s = 0.0f;
        for (int k = t; k < 1024; k += 256)
            s += identity[k] * freq_W[(size_t)k * 64 + n];
        red[t] = s;
        __syncthreads();
        for (int o = 128; o > 0; o >>= 1) {
            if (t < o) red[t] += red[t + o];
            __syncthreads();
        }
        if (t == 0) c1[n] = red[0];
    } else if (b < 5696) {     // Wc[n][k] = sum_j out_W[k,j] * Fcat[j,n]
        int bb = b - 3648;
        int n  = bb >> 4;
        int k  = (bb & 15) * 8 + (t >> 5);
        int lane = t & 31;
        float s = 0.0f;
        for (int j = lane; j < 1024; j += 32) {
            float fc = (n < 64) ? freq_W[(size_t)j * 64 + n]
                                : freq_W[(size_t)(1024 + j) * 64 + (n - 64)];
            s += out_W[(size_t)k * 1024 + j] * fc;
        }
        #pragma unroll
        for (int o = 16; o > 0; o >>= 1)
            s += __shfl_xor_sync(0xffffffff, s, o);
        if (lane == 0) Wc[(size_t)n * 128 + k] = __float2half_rn(s);
    } else {                   // cb[n] = out_b @ Fcat[:, n]
        __shared__ float red[256];
        int n = b - 5696;
        float s = 0.0f;
        for (int j = t; j < 1024; j += 256) {
            float fc = (n < 64) ? freq_W[(size_t)j * 64 + n]
                                : freq_W[(size_t)(1024 + j) * 64 + (n - 64)];
            s += out_b[j] * fc;
        }
        red[t] = s;
        __syncthreads();
        for (int o = 128; o > 0; o >>= 1) {
            if (t < o) red[t] += red[t + o];
            __syncthreads();
        }
        if (t == 0) cb[n] = red[0];
    }
}
// p = zh*rinv*v rounded to fp16 (proj A)
__global__ __launch_bounds__(256)
void mulround_k(const __half* __restrict__ zh, const float* __restrict__ pmax,
                const float* __restrict__ v, __half* __restrict__ ph)
{
    int wid = threadIdx.x >> 5, lane = threadIdx.x & 31;
    int r = blockIdx.x * 8 + wid;
    float rinv = get_rinv(pmax, r);
    #pragma unroll
    for (int j = 0; j < 8; j++) {
        int c = j * 128 + lane * 4;
        size_t b = (size_t)r * Cc + c;
        uint2 hw = *(const uint2*)&zh[b];
        float4 vv = *(const float4*)&v[b];
        float2 f0 = __half22float2(*(__half2*)&hw.x);
        float2 f1 = __half22float2(*(__half2*)&hw.y);
        uint2 o;
        o.x = roundH2(f0.x * rinv * vv.x, f0.y * rinv * vv.y);
        o.y = roundH2(f1.x * rinv * vv.z, f1.y * rinv * vv.w);
        *(uint2*)&ph[b] = o;
    }
}

// ---------------------------------------------------------------------------
extern "C" void kernel_launch(void* const* d_in, const int* in_sizes, int n_in,
                              void* d_out, int out_size)
{
    (void)in_sizes; (void)n_in; (void)out_size;
    const float* x        = (const float*)d_in[0];
    const float* attn_W   = (const float*)d_in[1];
    const float* attn_b   = (const float*)d_in[2];
    const float* freq_W   = (const float*)d_in[3];
    const float* freq_b   = (const float*)d_in[4];
    const float* out_W    = (const float*)d_in[5];
    const float* out_b    = (const float*)d_in[6];
    const float* proj_W   = (const float*)d_in[7];
    const float* proj_b   = (const float*)d_in[8];
    const float* identity = (const float*)d_in[9];

    __half *xh, *zh, *sch, *aW, *fW, *oW, *pW, *Wc;
    float *v, *u, *pmax, *c1, *cb, *zerob;
    cudaGetSymbolAddress((void**)&xh,  g_xh);
    cudaGetSymbolAddress((void**)&zh,  g_zh);
    cudaGetSymbolAddress((void**)&v,   g_v);   cudaGetSymbolAddress((void**)&u,   g_u);
    cudaGetSymbolAddress((void**)&sch, g_sch);
    cudaGetSymbolAddress((void**)&pmax,g_pmax);
    cudaGetSymbolAddress((void**)&c1,  g_c1);  cudaGetSymbolAddress((void**)&cb,  g_cb);
    cudaGetSymbolAddress((void**)&zerob, g_zero);
    cudaGetSymbolAddress((void**)&aW,  g_aW);  cudaGetSymbolAddress((void**)&fW,  g_fW);
    cudaGetSymbolAddress((void**)&oW,  g_oW);  cudaGetSymbolAddress((void**)&pW,  g_pW);
    cudaGetSymbolAddress((void**)&Wc,  g_Wc);

    const int SMB = 3 * 256 * 80;   // 61440
    cudaFuncSetAttribute(mma_gemm<0, 1024, 1024, 1024, 2048>,
                         cudaFuncAttributeMaxDynamicSharedMemorySize, SMB);
    cudaFuncSetAttribute(mma_gemm<1, 1024, 1024, 1024, 128>,
                         cudaFuncAttributeMaxDynamicSharedMemorySize, SMB);
    cudaFuncSetAttribute(mma_gemm<1, 1024, 1024, 1024, 1024>,
                         cudaFuncAttributeMaxDynamicSharedMemorySize, SMB);
    cudaFuncSetAttribute(outu_k<0>,
                         cudaFuncAttributeMaxDynamicSharedMemorySize, SMB);
    cudaFuncSetAttribute(outu_k<1>,
                         cudaFuncAttributeMaxDynamicSharedMemorySize, SMB);

    // prep
    cvt_k<<<8192, 256>>>(x, xh, MM * Cc);
    prep_w<<<5824, 256>>>(attn_W, freq_W, out_W, proj_W, identity, out_b,
                          aW, fW, oW, pW, Wc, c1, cb);

    // attn: qv = x @ attn_W + attn_b -> z0 (zh fp16) | v (fp32)
    mma_gemm<0, 1024, 1024, 1024, 2048><<<dim3(16, 128), 256, SMB>>>(
        xh, aW, attn_b, v, zh, nullptr);

    // U0 = z0 @ Fcat (one-time full freq GEMM)
    mma_gemm<1, 1024, 1024, 1024, 128><<<dim3(1, 128), 256, SMB>>>(
        zh, fW, zerob, u, nullptr, nullptr);

    // log-scan: combine + fused (out GEMM | U GEMM) per iteration.
    // Iterations 0..9: z is a dead store (only pmax is consumed) -> EPI 3.
    // Iteration 10 (last): write zh for proj, skip U tile.
    int iter = 0;
    for (int n = 1; n < Tt; n <<= 1, iter++) {
        combine_k<<<MM / 4, 256>>>(u, (iter == 0) ? nullptr : pmax,
                                   c1, freq_b, sch, n);
        if (iter < 10)
            outu_k<0><<<dim3(9, 128), 256, SMB>>>(sch, oW, Wc, out_b, cb,
                                                  zh, u, pmax);
        else
            outu_k<1><<<dim3(8, 128), 256, SMB>>>(sch, oW, Wc, out_b, cb,
                                                  zh, u, pmax);
    }

    // proj: out = (mmnorm(z) * v) @ proj_W + proj_b
    mulround_k<<<MM / 8, 256>>>(zh, pmax, v, xh);
    mma_gemm<1, 1024, 1024, 1024, 1024><<<dim3(8, 128), 256, SMB>>>(
        xh, pW, proj_b, (float*)d_out, nullptr, nullptr);
}